// round 6
// baseline (speedup 1.0000x reference)
#include <cuda_runtime.h>
#include <cstdint>

// ---------------------------------------------------------------------------
// TripletFeatures: M=41, p=20.  Index set: |m*n|<=20, n>=m, |m|+|n|<=20, K=173.
// out[b,c,k] = Re( S_mn * E[p+n,c] ) + (m!=n) * Re( S_nm * E[p+m,c] )
//   with S_xy = sum_c E[p+x,c]*conj(E[p+x+y,c])
// Output contract (verified R3): float32 (B, 2, K), REAL PART ONLY.
// ---------------------------------------------------------------------------

struct Tab { int n; unsigned pk[192]; };   // padded; pad entries are 0 (safe)

__host__ __device__ constexpr Tab make_tab() {
    Tab t{}; t.n = 0;
    for (int m = -20; m <= 20; ++m) {
        for (int n = -20; n <= 20; ++n) {
            int am = m < 0 ? -m : m;
            int an = n < 0 ? -n : n;
            if (am * an <= 20 && n >= m && am + an <= 20) {
                unsigned u = m + 20, v = n + 20, w = u + v - 20;
                t.pk[t.n] = u | (v << 8) | (w << 16);
                t.n = t.n + 1;
            }
        }
    }
    return t;
}

constexpr int K = make_tab().n;
static_assert(K == 173, "unexpected index-set size");

constexpr int WPB   = 8;     // warps (batches) per block
constexpr int NPOS  = 41;
constexpr int ME    = 82;    // floats per batch per input array
constexpr int KITER = 6;     // ceil(173/32)

__global__ void __launch_bounds__(WPB * 32, 4)   // <=64 regs: room to pipeline
triplet_kernel(const float* __restrict__ er,
               const float* __restrict__ ei,
               float* __restrict__ out,
               int B)
{
    static constexpr Tab TAB = make_tab();

    __shared__ float4   Esh[WPB][NPOS];   // (re0, im0, re1, im1) per position
    __shared__ unsigned tab_s[192];

    const int tid  = threadIdx.x;
    const int w    = tid >> 5;
    const int lane = tid & 31;
    const long long b = (long long)blockIdx.x * WPB + w;

    // Stage padded table (block-wide).
    if (tid < 192) tab_s[tid] = TAB.pk[tid];

    // Stage this warp's batch: coalesced float2 reads from each input array.
    if (b < B) {
        const float2* rb = reinterpret_cast<const float2*>(er + b * ME);
        const float2* ib = reinterpret_cast<const float2*>(ei + b * ME);
        #pragma unroll
        for (int j = lane; j < NPOS; j += 32) {
            const float2 r  = rb[j];
            const float2 im = ib[j];
            Esh[w][j] = make_float4(r.x, im.x, r.y, im.y);
        }
    }
    __syncthreads();
    if (b >= B) return;

    const float4* Eb = Esh[w];
    float* ob = out + b * (2 * K);

    // ---- software-pipelined k loop: prefetch i+1 while computing i --------
    unsigned pk = tab_s[lane];
    float4 U = Eb[pk & 0xff];
    float4 V = Eb[(pk >> 8) & 0xff];
    float4 W = Eb[(pk >> 16) & 0xff];

    #pragma unroll
    for (int i = 0; i < KITER; ++i) {
        unsigned npk = 0;
        float4 nU, nV, nW;
        if (i + 1 < KITER) {
            npk = tab_s[lane + 32 * (i + 1)];
            nU = Eb[npk & 0xff];
            nV = Eb[(npk >> 8) & 0xff];
            nW = Eb[(npk >> 16) & 0xff];
        }

        // S = sum_c U_c * conj(W_c)
        const float Sr = U.x * W.x + U.y * W.y + U.z * W.z + U.w * W.w;
        const float Si = U.y * W.x - U.x * W.y + U.w * W.z - U.z * W.w;

        float o0 = Sr * V.x - Si * V.y;       // Re(S * V0)
        float o1 = Sr * V.z - Si * V.w;       // Re(S * V1)

        if ((pk & 0xff) != ((pk >> 8) & 0xff)) {   // m != n: symmetric term
            const float Tr = V.x * W.x + V.y * W.y + V.z * W.z + V.w * W.w;
            const float Ti = V.y * W.x - V.x * W.y + V.w * W.z - V.z * W.w;
            o0 += Tr * U.x - Ti * U.y;
            o1 += Tr * U.z - Ti * U.w;
        }

        const int k = lane + 32 * i;
        if (k < K) {
            ob[k]     = o0;   // out[b, 0, k]
            ob[K + k] = o1;   // out[b, 1, k]
        }

        pk = npk; U = nU; V = nV; W = nW;
    }
}

extern "C" void kernel_launch(void* const* d_in, const int* in_sizes, int n_in,
                              void* d_out, int out_size)
{
    const float* er = (const float*)d_in[0];   // E_real (B, 41, 2) float32
    const float* ei = (const float*)d_in[1];   // E_imag (B, 41, 2) float32
    float* out = (float*)d_out;                // float32 (B, 2, K) real parts

    const int B = in_sizes[0] / ME;
    const int grid = (B + WPB - 1) / WPB;

    triplet_kernel<<<grid, WPB * 32>>>(er, ei, out, B);
}

// round 7
// speedup vs baseline: 1.0059x; 1.0059x over previous
#include <cuda_runtime.h>
#include <cstdint>

// ---------------------------------------------------------------------------
// TripletFeatures: M=41, p=20.  Index set: |m*n|<=20, n>=m, |m|+|n|<=20, K=173.
// out[b,c,k] = Re( S_mn * E[p+n,c] ) + (m!=n) * Re( S_nm * E[p+m,c] )
//   with S_xy = sum_c E[p+x,c]*conj(E[p+x+y,c])
// Output contract (verified R3): float32 (B, 2, K), REAL PART ONLY.
//
// Design: lanes = batches (uniform k per warp -> no divergence, no LDC replay,
// conflict-free padded smem), entries sorted by w=m+n for W-register reuse,
// output staged in smem for fully coalesced global stores.
// ---------------------------------------------------------------------------

constexpr int K     = 173;
constexpr int NPOS  = 41;
constexpr int BPB   = 32;    // batches per block
constexpr int THR   = 256;   // 8 warps
constexpr int ME    = 82;    // floats per batch per input array

struct STab { unsigned e[K]; };   // u | v<<8 | k_orig<<16, sorted by (u+v)

__host__ __device__ constexpr STab make_sorted_tab() {
    unsigned tmp[K] = {};
    int cnt = 0;
    for (int m = -20; m <= 20; ++m) {
        for (int n = -20; n <= 20; ++n) {
            int am = m < 0 ? -m : m;
            int an = n < 0 ? -n : n;
            if (am * an <= 20 && n >= m && am + an <= 20) {
                tmp[cnt] = (unsigned)((m + 20) | ((n + 20) << 8) | (cnt << 16));
                ++cnt;
            }
        }
    }
    // stable insertion sort by key u+v
    for (int i = 1; i < K; ++i) {
        unsigned x = tmp[i];
        int key = (int)(x & 0xff) + (int)((x >> 8) & 0xff);
        int j = i - 1;
        while (j >= 0) {
            int kj = (int)(tmp[j] & 0xff) + (int)((tmp[j] >> 8) & 0xff);
            if (kj <= key) break;
            tmp[j + 1] = tmp[j];
            --j;
        }
        tmp[j + 1] = x;
    }
    STab t{};
    for (int i = 0; i < K; ++i) t.e[i] = tmp[i];
    return t;
}

// smem layout (floats): Esh float4[41][33] then Osh float[346][33]
constexpr int ESH_F4    = NPOS * 33;            // 1353 float4
constexpr int OSH_BASE  = ESH_F4 * 4;           // float offset of Osh
constexpr int SMEM_FLOATS = OSH_BASE + 2 * K * 33;
constexpr int SMEM_BYTES  = SMEM_FLOATS * 4;    // 67320 B

__global__ void __launch_bounds__(THR, 3)
triplet_kernel(const float* __restrict__ er,
               const float* __restrict__ ei,
               float* __restrict__ out,
               int B)
{
    static constexpr STab TAB = make_sorted_tab();

    extern __shared__ float sm[];
    float4* Esh = reinterpret_cast<float4*>(sm);   // [pos*33 + batch]
    float*  Osh = sm + OSH_BASE;                   // [row*33 + batch], row=c*173+k

    const int tid   = threadIdx.x;
    const int w     = tid >> 5;
    const int lane  = tid & 31;
    const int bbase = blockIdx.x * BPB;

    // ---- stage 32 batches (coalesced float2 reads, conflict-free STS) -----
    {
        const float2* er2 = reinterpret_cast<const float2*>(er);
        const float2* ei2 = reinterpret_cast<const float2*>(ei);
        const long long g0 = (long long)bbase * NPOS;
        #pragma unroll
        for (int t = 0; t < 6; ++t) {
            int idx = tid + THR * t;            // idx = bl*41 + p
            if (idx < BPB * NPOS) {
                int bl = idx / NPOS;
                int p  = idx - bl * NPOS;
                if (bbase + bl < B) {
                    float2 r  = er2[g0 + idx];
                    float2 im = ei2[g0 + idx];
                    Esh[p * 33 + bl] = make_float4(r.x, im.x, r.y, im.y);
                }
            }
        }
    }
    __syncthreads();

    // ---- phase 1: uniform-k loop, lane = batch ----------------------------
    {
        const float4* EshL = Esh + lane;   // Esh[row*33 + lane]
        float*        oshL = Osh + lane;   // Osh[row*33 + lane]

        const int lo = (K * w) >> 3;
        const int hi = (K * (w + 1)) >> 3;

        float4 Wv = make_float4(0.f, 0.f, 0.f, 0.f);
        int wsprev = -1;

        for (int j = lo; j < hi; ++j) {
            const unsigned e = TAB.e[j];            // uniform const read
            const int u = e & 0xff;
            const int v = (e >> 8) & 0xff;
            const int k = (int)(e >> 16);
            const int ws = u + v - 20;

            if (ws != wsprev) {                     // uniform branch
                Wv = EshL[ws * 33];
                wsprev = ws;
            }
            const float4 U = EshL[u * 33];
            const float4 V = EshL[v * 33];

            const float Sr = U.x * Wv.x + U.y * Wv.y + U.z * Wv.z + U.w * Wv.w;
            const float Si = U.y * Wv.x - U.x * Wv.y + U.w * Wv.z - U.z * Wv.w;

            float o0 = Sr * V.x - Si * V.y;
            float o1 = Sr * V.z - Si * V.w;

            if (u != v) {                           // uniform branch
                const float Tr = V.x * Wv.x + V.y * Wv.y + V.z * Wv.z + V.w * Wv.w;
                const float Ti = V.y * Wv.x - V.x * Wv.y + V.w * Wv.z - V.z * Wv.w;
                o0 += Tr * U.x - Ti * U.y;
                o1 += Tr * U.z - Ti * U.w;
            }

            oshL[k * 33]           = o0;    // row k        (c = 0)
            oshL[(K + k) * 33]     = o1;    // row 173 + k  (c = 1)
        }
    }
    __syncthreads();

    // ---- phase 2: coalesced writeback (warp w owns batches 4w..4w+3) ------
    {
        #pragma unroll
        for (int jb = 0; jb < 4; ++jb) {
            const int bl = (w << 2) + jb;
            const long long b = (long long)bbase + bl;
            if (b < B) {
                float* ob = out + b * (2 * K);
                const float* osrc = Osh + bl;       // Osh[r*33 + bl]
                #pragma unroll
                for (int t = 0; t < 11; ++t) {
                    const int r = lane + 32 * t;
                    if (r < 2 * K) {
                        ob[r] = osrc[r * 33];
                    }
                }
            }
        }
    }
}

extern "C" void kernel_launch(void* const* d_in, const int* in_sizes, int n_in,
                              void* d_out, int out_size)
{
    const float* er = (const float*)d_in[0];   // E_real (B, 41, 2) float32
    const float* ei = (const float*)d_in[1];   // E_imag (B, 41, 2) float32
    float* out = (float*)d_out;                // float32 (B, 2, K) real parts

    const int B = in_sizes[0] / ME;
    const int grid = (B + BPB - 1) / BPB;

    cudaFuncSetAttribute(triplet_kernel,
                         cudaFuncAttributeMaxDynamicSharedMemorySize,
                         SMEM_BYTES);
    triplet_kernel<<<grid, THR, SMEM_BYTES>>>(er, ei, out, B);
}

// round 8
// speedup vs baseline: 1.0133x; 1.0074x over previous
#include <cuda_runtime.h>
#include <cstdint>

// ---------------------------------------------------------------------------
// TripletFeatures: M=41, p=20.  Index set: |m*n|<=20, n>=m, |m|+|n|<=20, K=173.
// out[b,c,k] = Re( S_mn * E[p+n,c] ) + (m!=n) * Re( S_nm * E[p+m,c] )
//   with S_xy = sum_c E[p+x,c]*conj(E[p+x+y,c])
// Output contract (verified R3): float32 (B, 2, K), REAL PART ONLY.
//
// Design: lane = batch (conflict-free smem, uniform k per warp -> broadcast
// table reads, uniform branches), natural m-major order gives U-register
// reuse, K chunked x4 so the output staging buffer stays small (33 KB total
// static smem -> 6 blocks/SM, 75% occupancy), coalesced chunk writeback.
// ---------------------------------------------------------------------------

constexpr int K     = 173;
constexpr int NPOS  = 41;
constexpr int BPB   = 32;    // batches per block (= lanes)
constexpr int THR   = 256;   // 8 warps
constexpr int ME    = 82;    // floats per batch per input array
constexpr int CMAX  = 44;    // chunk length (4 chunks: 44,44,44,41)
constexpr int OSROW = 33;    // padded batch stride (conflict-free)

struct Tab { unsigned e[K]; };   // u | v<<8 | w<<16, natural (m-major) order

__host__ __device__ constexpr Tab make_tab() {
    Tab t{}; int cnt = 0;
    for (int m = -20; m <= 20; ++m) {
        for (int n = -20; n <= 20; ++n) {
            int am = m < 0 ? -m : m;
            int an = n < 0 ? -n : n;
            if (am * an <= 20 && n >= m && am + an <= 20) {
                unsigned u = m + 20, v = n + 20, w = u + v - 20;
                t.e[cnt] = u | (v << 8) | (w << 16);
                ++cnt;
            }
        }
    }
    return t;
}

__global__ void __launch_bounds__(THR, 6)
triplet_kernel(const float* __restrict__ er,
               const float* __restrict__ ei,
               float* __restrict__ out,
               int B)
{
    static constexpr Tab TAB = make_tab();

    __shared__ float4 Esh[NPOS][OSROW];          // [pos][batch], 21.6 KB
    __shared__ float  Osh[2 * CMAX * OSROW];     // [c][kk][batch], 11.6 KB

    const int tid   = threadIdx.x;
    const int w     = tid >> 5;
    const int lane  = tid & 31;
    const int bbase = blockIdx.x * BPB;

    // ---- stage 32 batches: coalesced float2 reads, conflict-free STS ------
    {
        const float2* er2 = reinterpret_cast<const float2*>(er);
        const float2* ei2 = reinterpret_cast<const float2*>(ei);
        const long long g0 = (long long)bbase * NPOS;
        #pragma unroll
        for (int t = 0; t < 6; ++t) {
            const int idx = tid + THR * t;            // idx = bl*41 + p
            if (idx < BPB * NPOS) {
                const int bl = idx / NPOS;
                const int p  = idx - bl * NPOS;
                if (bbase + bl < B) {
                    const float2 r  = er2[g0 + idx];
                    const float2 im = ei2[g0 + idx];
                    Esh[p][bl] = make_float4(r.x, im.x, r.y, im.y);
                }
            }
        }
    }
    __syncthreads();

    // ---- chunked k loop ----------------------------------------------------
    for (int c0 = 0; c0 < K; c0 += CMAX) {
        const int clen = min(CMAX, K - c0);

        // compute: warp w owns kk in [w*6, w*6+6); uniform k across the warp
        {
            int uprev = -1;
            float4 U = make_float4(0.f, 0.f, 0.f, 0.f);
            #pragma unroll
            for (int t = 0; t < 6; ++t) {
                const int kk = w * 6 + t;
                if (kk < clen) {
                    const unsigned e = TAB.e[c0 + kk];   // uniform broadcast
                    const int u  = e & 0xff;
                    const int v  = (e >> 8) & 0xff;
                    const int ws = (e >> 16) & 0xff;

                    if (u != uprev) { U = Esh[u][lane]; uprev = u; }  // m-run reuse
                    const float4 V = Esh[v][lane];
                    const float4 W = Esh[ws][lane];

                    const float Sr = U.x * W.x + U.y * W.y + U.z * W.z + U.w * W.w;
                    const float Si = U.y * W.x - U.x * W.y + U.w * W.z - U.z * W.w;

                    float o0 = Sr * V.x - Si * V.y;
                    float o1 = Sr * V.z - Si * V.w;

                    if (u != v) {                        // uniform branch
                        const float Tr = V.x * W.x + V.y * W.y + V.z * W.z + V.w * W.w;
                        const float Ti = V.y * W.x - V.x * W.y + V.w * W.z - V.z * W.w;
                        o0 += Tr * U.x - Ti * U.y;
                        o1 += Tr * U.z - Ti * U.w;
                    }

                    Osh[kk * OSROW + lane]                  = o0;  // c = 0
                    Osh[CMAX * OSROW + kk * OSROW + lane]   = o1;  // c = 1
                }
            }
        }
        __syncthreads();

        // writeback: warp w owns batches 4w..4w+3; coalesced global stores
        {
            #pragma unroll
            for (int jb = 0; jb < 4; ++jb) {
                const int bl = (w << 2) + jb;
                const long long b = (long long)bbase + bl;
                if (b < B) {
                    float* ob = out + b * (2 * K) + c0;
                    #pragma unroll
                    for (int c = 0; c < 2; ++c) {
                        #pragma unroll
                        for (int t = 0; t < 2; ++t) {
                            const int kk = lane + 32 * t;
                            if (kk < clen) {
                                ob[c * K + kk] =
                                    Osh[c * CMAX * OSROW + kk * OSROW + bl];
                            }
                        }
                    }
                }
            }
        }
        __syncthreads();
    }
}

extern "C" void kernel_launch(void* const* d_in, const int* in_sizes, int n_in,
                              void* d_out, int out_size)
{
    const float* er = (const float*)d_in[0];   // E_real (B, 41, 2) float32
    const float* ei = (const float*)d_in[1];   // E_imag (B, 41, 2) float32
    float* out = (float*)d_out;                // float32 (B, 2, K) real parts

    const int B = in_sizes[0] / ME;
    const int grid = (B + BPB - 1) / BPB;

    triplet_kernel<<<grid, THR>>>(er, ei, out, B);
}

// round 9
// speedup vs baseline: 1.2347x; 1.2184x over previous
#include <cuda_runtime.h>
#include <cstdint>

// ---------------------------------------------------------------------------
// TripletFeatures: M=41, p=20.  Index set: |m*n|<=20, n>=m, |m|+|n|<=20, K=173.
// out[b,c,k] = Re( S_mn * E[p+n,c] ) + (m!=n) * Re( S_nm * E[p+m,c] )
//   with S_xy = sum_c E[p+x,c]*conj(E[p+x+y,c])
// Output contract (verified R3): float32 (B, 2, K), REAL PART ONLY.
//
// R3 skeleton (1 warp/batch, constexpr table, direct stores, warp-sync only)
// + float4 smem (8-lane LDS.128 phases) + compile-time bank-conflict-aware
// lane scheduling within each 32-k group (stores stay sector-coalesced).
// ---------------------------------------------------------------------------

constexpr int K     = 173;
constexpr int NPOS  = 41;
constexpr int WPB   = 8;     // warps (batches) per block
constexpr int ME    = 82;    // floats per batch per input array
constexpr int KITER = 6;     // 6*32 = 192 slots (19 pad)

struct Sched { unsigned e[192]; };   // u | v<<8 | w<<16 | k<<24 (k=255 = pad)

__host__ __device__ constexpr Sched make_sched() {
    // 1) raw entries in natural (m-major) order
    unsigned raw[192] = {};
    int cnt = 0;
    for (int m = -20; m <= 20; ++m) {
        for (int n = -20; n <= 20; ++n) {
            int am = m < 0 ? -m : m;
            int an = n < 0 ? -n : n;
            if (am * an <= 20 && n >= m && am + an <= 20) {
                unsigned u = m + 20, v = n + 20, w = u + v - 20;
                raw[cnt] = u | (v << 8) | (w << 16) | ((unsigned)cnt << 24);
                ++cnt;
            }
        }
    }
    for (int i = cnt; i < 192; ++i) raw[i] = (255u << 24);   // pads: u=v=w=0

    // 2) per 32-entry group: greedy assignment to 4 phases x 8 lanes,
    //    minimizing distinct-address mod-8 collisions for U, V, W.
    Sched s{};
    for (int g = 0; g < 6; ++g) {
        int phCnt[4] = {0, 0, 0, 0};
        int addr[4][3][8] = {};   // [phase][operand][slot] = address+1 (0=empty)
        int nA[4][3] = {};
        for (int j = 0; j < 32; ++j) {
            const unsigned e = raw[g * 32 + j];
            const int ops[3] = { (int)(e & 0xff), (int)((e >> 8) & 0xff),
                                 (int)((e >> 16) & 0xff) };
            int bestP = -1, bestCost = 1 << 30;
            for (int p = 0; p < 4; ++p) {
                if (phCnt[p] >= 8) continue;
                int cost = 0;
                for (int o = 0; o < 3; ++o) {
                    bool same = false; int coll = 0;
                    for (int t = 0; t < nA[p][o]; ++t) {
                        const int a = addr[p][o][t] - 1;
                        if (a == ops[o]) { same = true; break; }
                        if ((a & 7) == (ops[o] & 7)) ++coll;
                    }
                    if (!same) cost += coll;
                }
                if (cost < bestCost) { bestCost = cost; bestP = p; }
            }
            const int lane = bestP * 8 + phCnt[bestP];
            ++phCnt[bestP];
            for (int o = 0; o < 3; ++o) {
                bool same = false;
                for (int t = 0; t < nA[bestP][o]; ++t)
                    if (addr[bestP][o][t] - 1 == ops[o]) { same = true; break; }
                if (!same && nA[bestP][o] < 8)
                    addr[bestP][o][nA[bestP][o]++] = ops[o] + 1;
            }
            s.e[g * 32 + lane] = e;
        }
    }
    return s;
}

__global__ void __launch_bounds__(WPB * 32)
triplet_kernel(const float* __restrict__ er,
               const float* __restrict__ ei,
               float* __restrict__ out,
               int B)
{
    static constexpr Sched SCHED = make_sched();

    __shared__ float4 Esh[WPB][NPOS];   // (re0, im0, re1, im1) per position

    const int w    = threadIdx.x >> 5;
    const int lane = threadIdx.x & 31;
    const long long b = (long long)blockIdx.x * WPB + w;
    if (b >= B) return;

    // Stage this warp's batch: coalesced float2 reads, conflict-free STS.128.
    const float2* rb = reinterpret_cast<const float2*>(er + b * ME);
    const float2* ib = reinterpret_cast<const float2*>(ei + b * ME);
    #pragma unroll
    for (int j = lane; j < NPOS; j += 32) {
        const float2 r  = rb[j];
        const float2 im = ib[j];
        Esh[w][j] = make_float4(r.x, im.x, r.y, im.y);
    }
    __syncwarp();

    const float4* Eb = Esh[w];
    float* ob = out + b * (2 * K);

    #pragma unroll
    for (int i = 0; i < KITER; ++i) {
        const unsigned e = SCHED.e[lane + 32 * i];
        const int u  = e & 0xff;
        const int v  = (e >> 8) & 0xff;
        const int ws = (e >> 16) & 0xff;
        const int k  = (int)(e >> 24);

        const float4 U = Eb[u];
        const float4 V = Eb[v];
        const float4 W = Eb[ws];

        // S = sum_c U_c * conj(W_c)
        const float Sr = U.x * W.x + U.y * W.y + U.z * W.z + U.w * W.w;
        const float Si = U.y * W.x - U.x * W.y + U.w * W.z - U.z * W.w;

        float o0 = Sr * V.x - Si * V.y;       // Re(S * V0)
        float o1 = Sr * V.z - Si * V.w;       // Re(S * V1)

        if (u != v) {                          // symmetric term (m != n)
            const float Tr = V.x * W.x + V.y * W.y + V.z * W.z + V.w * W.w;
            const float Ti = V.y * W.x - V.x * W.y + V.w * W.z - V.z * W.w;
            o0 += Tr * U.x - Ti * U.y;
            o1 += Tr * U.z - Ti * U.w;
        }

        if (k < K) {
            ob[k]     = o0;   // out[b, 0, k]
            ob[K + k] = o1;   // out[b, 1, k]
        }
    }
}

extern "C" void kernel_launch(void* const* d_in, const int* in_sizes, int n_in,
                              void* d_out, int out_size)
{
    const float* er = (const float*)d_in[0];   // E_real (B, 41, 2) float32
    const float* ei = (const float*)d_in[1];   // E_imag (B, 41, 2) float32
    float* out = (float*)d_out;                // float32 (B, 2, K) real parts

    const int B = in_sizes[0] / ME;
    const int grid = (B + WPB - 1) / WPB;

    triplet_kernel<<<grid, WPB * 32>>>(er, ei, out, B);
}

// round 10
// speedup vs baseline: 1.3053x; 1.0573x over previous
#include <cuda_runtime.h>
#include <cstdint>

// ---------------------------------------------------------------------------
// TripletFeatures: M=41, p=20.  Index set: |m*n|<=20, n>=m, |m|+|n|<=20, K=173.
// out[b,c,k] = Re( S_mn * E[p+n,c] ) + (m!=n) * Re( S_nm * E[p+m,c] )
//   with S_xy = sum_c E[p+x,c]*conj(E[p+x+y,c])
// Output contract (verified R3): float32 (B, 2, K), REAL PART ONLY.
//
// Champion R3 structure (1 warp/batch, float2 smem, constexpr table, direct
// coalesced stores, warp-sync only) with decode/tail micro-trims.
// ---------------------------------------------------------------------------

constexpr int K    = 173;
constexpr int WPB  = 8;     // warps (batches) per block
constexpr int ME   = 82;    // floats per batch per input array (41 pos * 2 c)

struct Tab { unsigned short e[K]; };   // u | v<<8  (w = u+v-20 derived)

__host__ __device__ constexpr Tab make_tab() {
    Tab t{}; int cnt = 0;
    for (int m = -20; m <= 20; ++m) {
        for (int n = -20; n <= 20; ++n) {
            int am = m < 0 ? -m : m;
            int an = n < 0 ? -n : n;
            if (am * an <= 20 && n >= m && am + an <= 20) {
                t.e[cnt] = (unsigned short)((m + 20) | ((n + 20) << 8));
                ++cnt;
            }
        }
    }
    return t;
}

__global__ void __launch_bounds__(WPB * 32, 8)
triplet_kernel(const float* __restrict__ er,
               const float* __restrict__ ei,
               float* __restrict__ out,
               int B)
{
    static constexpr Tab TAB = make_tab();

    __shared__ float2 Esh[WPB][ME];   // (re, im) per (pos, comp)

    const int w    = threadIdx.x >> 5;
    const int lane = threadIdx.x & 31;
    const long long b = (long long)blockIdx.x * WPB + w;
    if (b >= B) return;

    // Stage this warp's batch (coalesced float reads from each input array).
    const float* rbase = er + b * ME;
    const float* ibase = ei + b * ME;
    #pragma unroll
    for (int j = lane; j < ME; j += 32)
        Esh[w][j] = make_float2(rbase[j], ibase[j]);
    __syncwarp();

    const float2* Eb = Esh[w];
    float* ob  = out + b * (2 * K);
    float* obK = ob + K;

    // 5 full 32-lane iterations (k = lane + 32*i < 160: no guard), then tail.
    #pragma unroll
    for (int i = 0; i < 5; ++i) {
        const int k = lane + 32 * i;
        const unsigned e = TAB.e[k];
        const int u  = e & 0xff;          // p + m
        const int v  = e >> 8;            // p + n
        const int ww = u + v - 20;        // p + m + n

        const float2 U0 = Eb[2 * u    ];
        const float2 U1 = Eb[2 * u + 1];
        const float2 V0 = Eb[2 * v    ];
        const float2 V1 = Eb[2 * v + 1];
        const float2 W0 = Eb[2 * ww    ];
        const float2 W1 = Eb[2 * ww + 1];

        const float Sr = U0.x * W0.x + U0.y * W0.y + U1.x * W1.x + U1.y * W1.y;
        const float Si = U0.y * W0.x - U0.x * W0.y + U1.y * W1.x - U1.x * W1.y;

        float o0 = Sr * V0.x - Si * V0.y;
        float o1 = Sr * V1.x - Si * V1.y;

        if (u != v) {
            const float Tr = V0.x * W0.x + V0.y * W0.y + V1.x * W1.x + V1.y * W1.y;
            const float Ti = V0.y * W0.x - V0.x * W0.y + V1.y * W1.x - V1.x * W1.y;
            o0 += Tr * U0.x - Ti * U0.y;
            o1 += Tr * U1.x - Ti * U1.y;
        }

        ob[k]  = o0;    // out[b, 0, k]
        obK[k] = o1;    // out[b, 1, k]
    }

    // Tail: k = 160 + lane, 13 active lanes.
    {
        const int k = 160 + lane;
        if (k < K) {
            const unsigned e = TAB.e[k];
            const int u  = e & 0xff;
            const int v  = e >> 8;
            const int ww = u + v - 20;

            const float2 U0 = Eb[2 * u    ];
            const float2 U1 = Eb[2 * u + 1];
            const float2 V0 = Eb[2 * v    ];
            const float2 V1 = Eb[2 * v + 1];
            const float2 W0 = Eb[2 * ww    ];
            const float2 W1 = Eb[2 * ww + 1];

            const float Sr = U0.x * W0.x + U0.y * W0.y + U1.x * W1.x + U1.y * W1.y;
            const float Si = U0.y * W0.x - U0.x * W0.y + U1.y * W1.x - U1.x * W1.y;

            float o0 = Sr * V0.x - Si * V0.y;
            float o1 = Sr * V1.x - Si * V1.y;

            if (u != v) {
                const float Tr = V0.x * W0.x + V0.y * W0.y + V1.x * W1.x + V1.y * W1.y;
                const float Ti = V0.y * W0.x - V0.x * W0.y + V1.y * W1.x - V1.x * W1.y;
                o0 += Tr * U0.x - Ti * U0.y;
                o1 += Tr * U1.x - Ti * U1.y;
            }

            ob[k]  = o0;
            obK[k] = o1;
        }
    }
}

extern "C" void kernel_launch(void* const* d_in, const int* in_sizes, int n_in,
                              void* d_out, int out_size)
{
    const float* er = (const float*)d_in[0];   // E_real (B, 41, 2) float32
    const float* ei = (const float*)d_in[1];   // E_imag (B, 41, 2) float32
    float* out = (float*)d_out;                // float32 (B, 2, K) real parts

    const int B = in_sizes[0] / ME;
    const int grid = (B + WPB - 1) / WPB;

    triplet_kernel<<<grid, WPB * 32>>>(er, ei, out, B);
}

// round 11
// speedup vs baseline: 1.3154x; 1.0077x over previous
#include <cuda_runtime.h>
#include <cstdint>

// ---------------------------------------------------------------------------
// TripletFeatures: M=41, p=20.  Index set: |m*n|<=20, n>=m, |m|+|n|<=20, K=173.
// out[b,c,k] = Re( S_mn * E[p+n,c] ) + (m!=n) * Re( S_nm * E[p+m,c] )
//   with S_xy = sum_c E[p+x,c]*conj(E[p+x+y,c])
// Output contract (verified): float32 (B, 2, K), REAL PART ONLY.
//
// Persistent grid-stride warps (no wave transitions) + register-prefetched
// double-buffered staging (global latency hidden behind the k-loop).
// k-loop identical to the R10 champion.
// ---------------------------------------------------------------------------

constexpr int K    = 173;
constexpr int WPB  = 8;     // warps per block
constexpr int ME   = 82;    // floats per batch per input array (41 pos * 2 c)

struct Tab { unsigned short e[K]; };   // u | v<<8  (w = u+v-20 derived)

__host__ __device__ constexpr Tab make_tab() {
    Tab t{}; int cnt = 0;
    for (int m = -20; m <= 20; ++m) {
        for (int n = -20; n <= 20; ++n) {
            int am = m < 0 ? -m : m;
            int an = n < 0 ? -n : n;
            if (am * an <= 20 && n >= m && am + an <= 20) {
                t.e[cnt] = (unsigned short)((m + 20) | ((n + 20) << 8));
                ++cnt;
            }
        }
    }
    return t;
}

__device__ __forceinline__ void compute_batch(const float2* __restrict__ Eb,
                                              float* __restrict__ ob,
                                              int lane)
{
    static constexpr Tab TAB = make_tab();
    float* obK = ob + K;

    #pragma unroll
    for (int i = 0; i < 6; ++i) {
        const int k = lane + 32 * i;
        if (i < 5 || k < K) {              // iterations 0..4 unguarded
            const unsigned e = TAB.e[k];
            const int u  = e & 0xff;       // p + m
            const int v  = e >> 8;         // p + n
            const int ww = u + v - 20;     // p + m + n

            const float2 U0 = Eb[2 * u    ];
            const float2 U1 = Eb[2 * u + 1];
            const float2 V0 = Eb[2 * v    ];
            const float2 V1 = Eb[2 * v + 1];
            const float2 W0 = Eb[2 * ww    ];
            const float2 W1 = Eb[2 * ww + 1];

            const float Sr = U0.x * W0.x + U0.y * W0.y + U1.x * W1.x + U1.y * W1.y;
            const float Si = U0.y * W0.x - U0.x * W0.y + U1.y * W1.x - U1.x * W1.y;

            float o0 = Sr * V0.x - Si * V0.y;
            float o1 = Sr * V1.x - Si * V1.y;

            if (u != v) {
                const float Tr = V0.x * W0.x + V0.y * W0.y + V1.x * W1.x + V1.y * W1.y;
                const float Ti = V0.y * W0.x - V0.x * W0.y + V1.y * W1.x - V1.x * W1.y;
                o0 += Tr * U0.x - Ti * U0.y;
                o1 += Tr * U1.x - Ti * U1.y;
            }

            ob[k]  = o0;    // out[b, 0, k]
            obK[k] = o1;    // out[b, 1, k]
        }
    }
}

__global__ void __launch_bounds__(WPB * 32, 6)
triplet_kernel(const float* __restrict__ er,
               const float* __restrict__ ei,
               float* __restrict__ out,
               int B, int warp_stride)
{
    __shared__ float2 Esh[WPB][2][ME];   // double-buffered per-warp staging

    const int w    = threadIdx.x >> 5;
    const int lane = threadIdx.x & 31;
    long long b = (long long)blockIdx.x * WPB + w;
    if (b >= B) return;

    // Prefetch first batch into registers (lane covers j, j+32, j+64).
    float pr[3], pi[3];
    {
        const float* rb = er + b * ME;
        const float* ib = ei + b * ME;
        #pragma unroll
        for (int t = 0; t < 3; ++t) {
            const int j = lane + 32 * t;
            if (t < 2 || j < ME) { pr[t] = __ldg(rb + j); pi[t] = __ldg(ib + j); }
        }
    }

    int buf = 0;
    while (true) {
        // Commit prefetched registers into the current staging buffer.
        #pragma unroll
        for (int t = 0; t < 3; ++t) {
            const int j = lane + 32 * t;
            if (t < 2 || j < ME) Esh[w][buf][j] = make_float2(pr[t], pi[t]);
        }

        // Launch next batch's global loads (overlap with this batch's compute).
        const long long bn = b + warp_stride;
        if (bn < B) {
            const float* rb = er + bn * ME;
            const float* ib = ei + bn * ME;
            #pragma unroll
            for (int t = 0; t < 3; ++t) {
                const int j = lane + 32 * t;
                if (t < 2 || j < ME) { pr[t] = __ldg(rb + j); pi[t] = __ldg(ib + j); }
            }
        }

        __syncwarp();
        compute_batch(Esh[w][buf], out + b * (2 * K), lane);

        if (bn >= B) break;
        b = bn;
        buf ^= 1;
        // Double buffer + the single per-iteration __syncwarp gives safe
        // ordering: the next write to this buffer is two syncs away.
    }
}

extern "C" void kernel_launch(void* const* d_in, const int* in_sizes, int n_in,
                              void* d_out, int out_size)
{
    const float* er = (const float*)d_in[0];   // E_real (B, 41, 2) float32
    const float* ei = (const float*)d_in[1];   // E_imag (B, 41, 2) float32
    float* out = (float*)d_out;                // float32 (B, 2, K) real parts

    const int B = in_sizes[0] / ME;

    int sms = 148;
    cudaDeviceGetAttribute(&sms, cudaDevAttrMultiProcessorCount, 0);
    int grid = sms * 6;                        // persistent-resident target
    const int maxg = (B + WPB - 1) / WPB;
    if (grid > maxg) grid = maxg;
    const int warp_stride = grid * WPB;

    triplet_kernel<<<grid, WPB * 32>>>(er, ei, out, B, warp_stride);
}